// round 14
// baseline (speedup 1.0000x reference)
#include <cuda_runtime.h>
#include <cuda_bf16.h>
#include <cstdint>

#define B_SZ   128
#define NNODES 2047
#define LEAVES 1024
#define DIN    512
#define NL     64
#define MROWS  (B_SZ * NNODES)          // 262016
#define NCHUNK 1024                     // 256-row GEMM chunks

typedef unsigned long long u64;

// ---------------- device scratch (static; no allocations) ----------------
__device__ float g_emis[(size_t)B_SZ * NNODES * NL];   // 67 MB
__device__ float g_bufA[(size_t)B_SZ * 512 * NL];      // odd levels
__device__ float g_bufB[(size_t)B_SZ * 256 * NL];      // even levels
__device__ uint4 g_Wfrag4[32 * 4 * 32];                // GEMM W frags, k-permuted
__device__ uint4 g_Tfrag[4 * 8 * 32];                  // tree expT frags {xh,yh,xl,yl}
__device__ int   g_ctr;                                // GEMM work-stealing counter

// ---------------- packed helpers ----------------
__device__ __forceinline__ uint32_t cvt_bf2(float x0, float x1) {
    uint32_t h;
    asm("cvt.rn.satfinite.bf16x2.f32 %0, %1, %2;" : "=r"(h) : "f"(x1), "f"(x0));
    return h;
}
__device__ __forceinline__ void cvt_hilo(float x0, float x1, uint32_t& h, uint32_t& l) {
    asm("cvt.rn.satfinite.bf16x2.f32 %0, %1, %2;" : "=r"(h) : "f"(x1), "f"(x0));
    float r0 = x0 - __uint_as_float(h << 16);
    float r1 = x1 - __uint_as_float(h & 0xffff0000u);
    asm("cvt.rn.satfinite.bf16x2.f32 %0, %1, %2;" : "=r"(l) : "f"(r1), "f"(r0));
}
__device__ __forceinline__ void mma16816(float& d0, float& d1, float& d2, float& d3,
                                         uint32_t a0, uint32_t a1, uint32_t a2, uint32_t a3,
                                         uint32_t b0, uint32_t b1) {
    asm("mma.sync.aligned.m16n8k16.row.col.f32.bf16.bf16.f32 "
        "{%0,%1,%2,%3}, {%4,%5,%6,%7}, {%8,%9}, {%0,%1,%2,%3};"
        : "+f"(d0), "+f"(d1), "+f"(d2), "+f"(d3)
        : "r"(a0), "r"(a1), "r"(a2), "r"(a3), "r"(b0), "r"(b1));
}

// ---------------- init: GEMM W frags + tree expT frags (hi/lo) ----------------
__global__ void init_kernel(const float* __restrict__ trans, const float* __restrict__ W) {
    int i = blockIdx.x * blockDim.x + threadIdx.x;
    if (i < 4 * 8 * 32) {
        int lane = i & 31, nt = (i >> 5) & 7, s = i >> 8;
        int n  = nt * 8 + (lane >> 2);
        int k0 = s * 16 + (lane & 3) * 4;
        float t0 = expf(trans[n * NL + k0]);
        float t1 = expf(trans[n * NL + k0 + 1]);
        float t2 = expf(trans[n * NL + k0 + 2]);
        float t3 = expf(trans[n * NL + k0 + 3]);
        uint32_t xh, xl, yh, yl;
        cvt_hilo(t0, t1, xh, xl);
        cvt_hilo(t2, t3, yh, yl);
        g_Tfrag[i] = make_uint4(xh, yh, xl, yl);
    }
    int j = i - 2048;
    if (j >= 0 && j < 32 * 4 * 32) {
        int lane = j & 31, tp = (j >> 5) & 3, s = j >> 7;
        int k0 = s * 16 + (lane & 3) * 4;            // permuted: contiguous quad
        int n0 = (2 * tp) * 8 + (lane >> 2);
        int n1 = (2 * tp + 1) * 8 + (lane >> 2);
        uint32_t x0 = cvt_bf2(W[k0 * NL + n0],       W[(k0 + 1) * NL + n0]);
        uint32_t y0 = cvt_bf2(W[(k0 + 2) * NL + n0], W[(k0 + 3) * NL + n0]);
        uint32_t x1 = cvt_bf2(W[k0 * NL + n1],       W[(k0 + 1) * NL + n1]);
        uint32_t y1 = cvt_bf2(W[(k0 + 2) * NL + n1], W[(k0 + 3) * NL + n1]);
        g_Wfrag4[j] = make_uint4(x0, y0, x1, y1);
    }
}

// ---------------- persistent HMMA emission GEMM: emis = hidden @ W + b ----------------
// 148 CTAs x 512 threads; 256-row chunks (1024 total, ~6.9/SM -> ~1% tail waste).
// Warp owns one m16 tile: rows chunk*256 + w*16 + {qr, qr+8}.
#define GS_TOTAL (65536 + 256)

extern __shared__ char dynsm[];

__global__ __launch_bounds__(512) void gemm_kernel(
    const float* __restrict__ A, const float* __restrict__ bias,
    float* __restrict__ out)
{
    uint4* Wsm = (uint4*)dynsm;
    float* bsm = (float*)(dynsm + 65536);
    __shared__ int s_ch;
    int tid = threadIdx.x;
    {
        const uint4* src = g_Wfrag4;
        for (int i = tid; i < 4096; i += 512) Wsm[i] = src[i];
        if (tid < NL) bsm[tid] = bias[tid];
    }
    __syncthreads();

    int lane = tid & 31, w = tid >> 5;
    int qr = lane >> 2;
    int qk = lane & 3;

    for (;;) {
        if (tid == 0) s_ch = atomicAdd(&g_ctr, 1);
        __syncthreads();
        int ch = s_ch;
        if (ch >= NCHUNK) break;

        long rowbase = (long)ch * 256 + w * 16;

        const float4* aptr[2];
#pragma unroll
        for (int rh = 0; rh < 2; ++rh) {
            long r = rowbase + rh * 8 + qr;
            if (r > MROWS - 1) r = MROWS - 1;
            aptr[rh] = (const float4*)(A + r * DIN) + qk;
        }

        float acc[8][4];
#pragma unroll
        for (int t = 0; t < 8; ++t)
#pragma unroll
            for (int e = 0; e < 4; ++e) acc[t][e] = 0.f;

        float4 buf[2][2];
#pragma unroll
        for (int p = 0; p < 2; ++p) {
            buf[0][p] = aptr[p][0];
            buf[1][p] = aptr[p][4];
        }

#pragma unroll 1
        for (int s = 0; s < 32; ++s) {
            int pb = s & 1;
            float4 v0 = buf[pb][0];
            float4 v1 = buf[pb][1];
            uint32_t a0 = cvt_bf2(v0.x, v0.y);
            uint32_t a1 = cvt_bf2(v1.x, v1.y);
            uint32_t a2 = cvt_bf2(v0.z, v0.w);
            uint32_t a3 = cvt_bf2(v1.z, v1.w);
            if (s + 2 < 32) {
#pragma unroll
                for (int p = 0; p < 2; ++p) buf[pb][p] = aptr[p][(s + 2) * 4];
            }
#pragma unroll
            for (int tp = 0; tp < 4; ++tp) {
                uint4 wb = Wsm[(s * 4 + tp) * 32 + lane];
                mma16816(acc[2*tp][0],   acc[2*tp][1],   acc[2*tp][2],   acc[2*tp][3],
                         a0, a1, a2, a3, wb.x, wb.y);
                mma16816(acc[2*tp+1][0], acc[2*tp+1][1], acc[2*tp+1][2], acc[2*tp+1][3],
                         a0, a1, a2, a3, wb.z, wb.w);
            }
        }

        int qkc = qk * 2;
#pragma unroll
        for (int rh = 0; rh < 2; ++rh) {
            long r = rowbase + rh * 8 + qr;
            if (r < MROWS) {
                float* orow = out + r * NL;
#pragma unroll
                for (int t = 0; t < 8; ++t) {
                    int c = t * 8 + qkc;
                    float2 v;
                    v.x = acc[t][rh * 2 + 0] + bsm[c];
                    v.y = acc[t][rh * 2 + 1] + bsm[c + 1];
                    *(float2*)(orow + c) = v;
                }
            }
        }
        __syncthreads();   // all threads consumed s_ch before next overwrite
    }
}

// ---------------- fused tree kernel: HMMA merge (R12 best: 84us) ----------------
#define EPITCH 34
#define TS_E    16384
#define TS_MBUF (TS_E + 256 * EPITCH * 8)            // 86016
#define TREE_SMEM_BYTES (TS_MBUF + 1024)             // 87040

__global__ __launch_bounds__(512) void tree_kernel(
    const float* __restrict__ emis, float* __restrict__ bufA,
    float* __restrict__ bufB, float* __restrict__ outg)
{
    uint4* Tsm = (uint4*)dynsm;
    float* Ebase = (float*)(dynsm + TS_E);           // pitch 68 floats per cv row
    float* mbuf = (float*)(dynsm + TS_MBUF);

    int t = threadIdx.x;
    int b = blockIdx.x;

    for (int i = t; i < 1024; i += 512) Tsm[i] = g_Tfrag[i];
    __syncthreads();

    const float* emisb = emis + (size_t)b * NNODES * NL;
    const float* prev  = emisb + (size_t)(LEAVES - 1) * NL;
    float* bufAb = bufA + (size_t)b * 512 * NL;
    float* bufBb = bufB + (size_t)b * 256 * NL;

    int lane = t & 31, w = t >> 5;
    int qr = lane >> 2, qk = lane & 3;
    int m0 = w * 16;
    bool gEven = (qr & 1) == 0;
    int sub = t & 3, cquad = t >> 2;

    for (int d = 9; d >= 0; --d) {
        int n = 1 << d;
        const float* emisLvl = emisb + (size_t)(n - 1) * NL;
        float* outLvl = (d == 0) ? (outg + (size_t)b * NL)
                                 : ((d & 1) ? bufAb : bufBb);
        int ntiles = (n + 127) >> 7;
        for (int tile = 0; tile < ntiles; ++tile) {
            int i0 = tile << 7;
            int NT = n - i0; if (NT > 128) NT = 128;
            int ncv = 2 * NT;

            // ---- phase 1: load children, per-cv max, exp, store f32 to E ----
            auto phase1 = [&](int co) {
                int c = co + cquad;
                bool valid = c < ncv;
                int cc = valid ? c : 0;
                const float* src = prev + (size_t)(i0 * 2 + cc) * NL + sub * 16;
                float4 v0 = *(const float4*)(src);
                float4 v1 = *(const float4*)(src + 4);
                float4 v2 = *(const float4*)(src + 8);
                float4 v3 = *(const float4*)(src + 12);
                float vv[16] = {v0.x, v0.y, v0.z, v0.w, v1.x, v1.y, v1.z, v1.w,
                                v2.x, v2.y, v2.z, v2.w, v3.x, v3.y, v3.z, v3.w};
                float m = vv[0];
#pragma unroll
                for (int j = 1; j < 16; ++j) m = fmaxf(m, vv[j]);
                m = fmaxf(m, __shfl_xor_sync(0xffffffffu, m, 1));
                m = fmaxf(m, __shfl_xor_sync(0xffffffffu, m, 2));
                if (valid) {
                    float* erow = Ebase + c * (EPITCH * 2) + sub * 16;
#pragma unroll
                    for (int j = 0; j < 4; ++j) {
                        float4 ev;
                        ev.x = __expf(vv[4 * j]     - m);
                        ev.y = __expf(vv[4 * j + 1] - m);
                        ev.z = __expf(vv[4 * j + 2] - m);
                        ev.w = __expf(vv[4 * j + 3] - m);
                        *(float4*)(erow + 4 * j) = ev;
                    }
                    if (sub == 0) mbuf[c] = m;
                }
            };
            phase1(0);
            if (ncv > 128) phase1(128);
            __syncthreads();

            // ---- phase 2: warp-level HMMA merge (warp owns 16 cv rows) ----
            if (m0 < ncv) {
                float acc[8][4];
#pragma unroll
                for (int nt = 0; nt < 8; ++nt)
#pragma unroll
                    for (int e = 0; e < 4; ++e) acc[nt][e] = 0.f;

#pragma unroll
                for (int s = 0; s < 4; ++s) {
                    const float* ep = Ebase + (m0 + qr) * (EPITCH * 2) + s * 16 + qk * 4;
                    float4 va = *(const float4*)(ep);
                    float4 vb = *(const float4*)(ep + 8 * EPITCH * 2);
                    uint32_t a0 = cvt_bf2(va.x, va.y);
                    uint32_t a1 = cvt_bf2(vb.x, vb.y);
                    uint32_t a2 = cvt_bf2(va.z, va.w);
                    uint32_t a3 = cvt_bf2(vb.z, vb.w);
#pragma unroll
                    for (int nt = 0; nt < 8; ++nt) {
                        uint4 wf = Tsm[(s * 8 + nt) * 32 + lane];
                        mma16816(acc[nt][0], acc[nt][1], acc[nt][2], acc[nt][3],
                                 a0, a1, a2, a3, wf.x, wf.y);   // hi
                        mma16816(acc[nt][0], acc[nt][1], acc[nt][2], acc[nt][3],
                                 a0, a1, a2, a3, wf.z, wf.w);   // lo
                    }
                }

                // ---- epilogue: log + m, combine L/R via shfl_xor(4), store ----
                int cvA = m0 + qr, cvB = m0 + qr + 8;
                float mA = mbuf[cvA], mB = mbuf[cvB];
                int nodeA = i0 + (cvA >> 1), nodeB = i0 + (cvB >> 1);
                int col = qk * 2;
#pragma unroll
                for (int nt = 0; nt < 8; ++nt) {
                    float l0 = __logf(acc[nt][0]) + mA;
                    float l1 = __logf(acc[nt][1]) + mA;
                    float l2 = __logf(acc[nt][2]) + mB;
                    float l3 = __logf(acc[nt][3]) + mB;
                    float o0 = __shfl_xor_sync(0xffffffffu, l0, 4);
                    float o1 = __shfl_xor_sync(0xffffffffu, l1, 4);
                    float o2 = __shfl_xor_sync(0xffffffffu, l2, 4);
                    float o3 = __shfl_xor_sync(0xffffffffu, l3, 4);
                    if (gEven) {
                        int c0 = nt * 8 + col;
                        if (cvA < ncv) {
                            float2 em = *(const float2*)(emisLvl + (size_t)nodeA * NL + c0);
                            float2 v; v.x = em.x + l0 + o0; v.y = em.y + l1 + o1;
                            *(float2*)(outLvl + (size_t)nodeA * NL + c0) = v;
                        }
                        if (cvB < ncv) {
                            float2 em = *(const float2*)(emisLvl + (size_t)nodeB * NL + c0);
                            float2 v; v.x = em.x + l2 + o2; v.y = em.y + l3 + o3;
                            *(float2*)(outLvl + (size_t)nodeB * NL + c0) = v;
                        }
                    }
                }
            }
            __syncthreads();
        }
        prev = outLvl;
    }
}

// ---------------- launch ----------------
extern "C" void kernel_launch(void* const* d_in, const int* in_sizes, int n_in,
                              void* d_out, int out_size)
{
    const float* hidden = (const float*)d_in[0];
    const float* W      = (const float*)d_in[1];
    const float* bias   = (const float*)d_in[2];
    const float* trans  = (const float*)d_in[3];
    float* out = (float*)d_out;

    float *emis, *bufA, *bufB;
    int* ctr;
    cudaGetSymbolAddress((void**)&emis, g_emis);
    cudaGetSymbolAddress((void**)&bufA, g_bufA);
    cudaGetSymbolAddress((void**)&bufB, g_bufB);
    cudaGetSymbolAddress((void**)&ctr,  g_ctr);

    cudaMemsetAsync(ctr, 0, sizeof(int));

    init_kernel<<<(2048 + 32 * 4 * 32 + 255) / 256, 256>>>(trans, W);

    cudaFuncSetAttribute(gemm_kernel, cudaFuncAttributeMaxDynamicSharedMemorySize, GS_TOTAL);
    gemm_kernel<<<148, 512, GS_TOTAL>>>(hidden, bias, emis);

    cudaFuncSetAttribute(tree_kernel, cudaFuncAttributeMaxDynamicSharedMemorySize, TREE_SMEM_BYTES);
    tree_kernel<<<B_SZ, 512, TREE_SMEM_BYTES>>>(emis, bufA, bufB, out);
}

// round 15
// speedup vs baseline: 1.3238x; 1.3238x over previous
#include <cuda_runtime.h>
#include <cuda_bf16.h>
#include <cstdint>

#define B_SZ   128
#define NNODES 2047
#define LEAVES 1024
#define DIN    512
#define NL     64
#define MROWS  (B_SZ * NNODES)          // 262016

typedef unsigned long long u64;

// ---------------- device scratch (static; no allocations) ----------------
__device__ float g_emis[(size_t)B_SZ * NNODES * NL];   // 67 MB
__device__ float g_bufA[(size_t)B_SZ * 512 * NL];      // odd levels
__device__ float g_bufB[(size_t)B_SZ * 256 * NL];      // even levels
__device__ uint4 g_Wfrag4[32 * 4 * 32];                // GEMM W frags, k-permuted
__device__ uint4 g_Tfrag[4 * 8 * 32];                  // tree expT frags {xh,yh,xl,yl}

// ---------------- packed helpers ----------------
__device__ __forceinline__ uint32_t cvt_bf2(float x0, float x1) {
    uint32_t h;
    asm("cvt.rn.satfinite.bf16x2.f32 %0, %1, %2;" : "=r"(h) : "f"(x1), "f"(x0));
    return h;
}
__device__ __forceinline__ void cvt_hilo(float x0, float x1, uint32_t& h, uint32_t& l) {
    asm("cvt.rn.satfinite.bf16x2.f32 %0, %1, %2;" : "=r"(h) : "f"(x1), "f"(x0));
    float r0 = x0 - __uint_as_float(h << 16);
    float r1 = x1 - __uint_as_float(h & 0xffff0000u);
    asm("cvt.rn.satfinite.bf16x2.f32 %0, %1, %2;" : "=r"(l) : "f"(r1), "f"(r0));
}
__device__ __forceinline__ void mma16816(float& d0, float& d1, float& d2, float& d3,
                                         uint32_t a0, uint32_t a1, uint32_t a2, uint32_t a3,
                                         uint32_t b0, uint32_t b1) {
    asm("mma.sync.aligned.m16n8k16.row.col.f32.bf16.bf16.f32 "
        "{%0,%1,%2,%3}, {%4,%5,%6,%7}, {%8,%9}, {%0,%1,%2,%3};"
        : "+f"(d0), "+f"(d1), "+f"(d2), "+f"(d3)
        : "r"(a0), "r"(a1), "r"(a2), "r"(a3), "r"(b0), "r"(b1));
}

// ---------------- init: GEMM W frags + tree expT frags (hi/lo) ----------------
__global__ void init_kernel(const float* __restrict__ trans, const float* __restrict__ W) {
    int i = blockIdx.x * blockDim.x + threadIdx.x;
    if (i < 4 * 8 * 32) {
        int lane = i & 31, nt = (i >> 5) & 7, s = i >> 8;
        int n  = nt * 8 + (lane >> 2);
        int k0 = s * 16 + (lane & 3) * 4;
        float t0 = expf(trans[n * NL + k0]);
        float t1 = expf(trans[n * NL + k0 + 1]);
        float t2 = expf(trans[n * NL + k0 + 2]);
        float t3 = expf(trans[n * NL + k0 + 3]);
        uint32_t xh, xl, yh, yl;
        cvt_hilo(t0, t1, xh, xl);
        cvt_hilo(t2, t3, yh, yl);
        g_Tfrag[i] = make_uint4(xh, yh, xl, yl);
    }
    int j = i - 2048;
    if (j >= 0 && j < 32 * 4 * 32) {
        int lane = j & 31, tp = (j >> 5) & 3, s = j >> 7;
        int k0 = s * 16 + (lane & 3) * 4;            // permuted: contiguous quad
        int n0 = (2 * tp) * 8 + (lane >> 2);
        int n1 = (2 * tp + 1) * 8 + (lane >> 2);
        uint32_t x0 = cvt_bf2(W[k0 * NL + n0],       W[(k0 + 1) * NL + n0]);
        uint32_t y0 = cvt_bf2(W[(k0 + 2) * NL + n0], W[(k0 + 3) * NL + n0]);
        uint32_t x1 = cvt_bf2(W[k0 * NL + n1],       W[(k0 + 1) * NL + n1]);
        uint32_t y1 = cvt_bf2(W[(k0 + 2) * NL + n1], W[(k0 + 3) * NL + n1]);
        g_Wfrag4[j] = make_uint4(x0, y0, x1, y1);
    }
}

// ---------------- HMMA emission GEMM (R12 best config) ----------------
// CTA = 512 rows, 16 warps x 32 rows (2 m16 tiles). Single-product bf16 MMA.
// k-permuted A fragments: one LDG.128 per row-group per kstep (line-minimal).
#define GS_TOTAL (65536 + 256)

extern __shared__ char dynsm[];

__global__ __launch_bounds__(512) void gemm_kernel(
    const float* __restrict__ A, const float* __restrict__ bias,
    float* __restrict__ out)
{
    uint4* Wsm = (uint4*)dynsm;
    float* bsm = (float*)(dynsm + 65536);
    int tid = threadIdx.x;
    {
        const uint4* src = g_Wfrag4;
        for (int i = tid; i < 4096; i += 512) Wsm[i] = src[i];
        if (tid < NL) bsm[tid] = bias[tid];
    }
    __syncthreads();

    int lane = tid & 31, w = tid >> 5;
    long rowbase = (long)blockIdx.x * 512 + w * 32;
    int qr = lane >> 2;
    int qk = lane & 3;

    const float4* aptr[4];
#pragma unroll
    for (int rt = 0; rt < 2; ++rt)
#pragma unroll
        for (int rh = 0; rh < 2; ++rh) {
            long r = rowbase + rt * 16 + rh * 8 + qr;
            if (r > MROWS - 1) r = MROWS - 1;
            aptr[rt * 2 + rh] = (const float4*)(A + r * DIN) + qk;
        }

    float acc[2][8][4];
#pragma unroll
    for (int rt = 0; rt < 2; ++rt)
#pragma unroll
        for (int t = 0; t < 8; ++t)
#pragma unroll
            for (int e = 0; e < 4; ++e) acc[rt][t][e] = 0.f;

    float4 buf[2][4];
#pragma unroll
    for (int p = 0; p < 4; ++p) {
        buf[0][p] = aptr[p][0];
        buf[1][p] = aptr[p][4];
    }

#pragma unroll 1
    for (int s = 0; s < 32; ++s) {
        int pb = s & 1;
        uint32_t ah[2][4];
#pragma unroll
        for (int rt = 0; rt < 2; ++rt) {
            float4 v0 = buf[pb][2 * rt];
            float4 v1 = buf[pb][2 * rt + 1];
            ah[rt][0] = cvt_bf2(v0.x, v0.y);
            ah[rt][1] = cvt_bf2(v1.x, v1.y);
            ah[rt][2] = cvt_bf2(v0.z, v0.w);
            ah[rt][3] = cvt_bf2(v1.z, v1.w);
        }
        if (s + 2 < 32) {
#pragma unroll
            for (int p = 0; p < 4; ++p) buf[pb][p] = aptr[p][(s + 2) * 4];
        }
#pragma unroll
        for (int tp = 0; tp < 4; ++tp) {
            uint4 wb = Wsm[(s * 4 + tp) * 32 + lane];
#pragma unroll
            for (int rt = 0; rt < 2; ++rt) {
                mma16816(acc[rt][2*tp][0],   acc[rt][2*tp][1],   acc[rt][2*tp][2],   acc[rt][2*tp][3],
                         ah[rt][0], ah[rt][1], ah[rt][2], ah[rt][3], wb.x, wb.y);
                mma16816(acc[rt][2*tp+1][0], acc[rt][2*tp+1][1], acc[rt][2*tp+1][2], acc[rt][2*tp+1][3],
                         ah[rt][0], ah[rt][1], ah[rt][2], ah[rt][3], wb.z, wb.w);
            }
        }
    }

    int qkc = qk * 2;
#pragma unroll
    for (int rt = 0; rt < 2; ++rt)
#pragma unroll
        for (int rh = 0; rh < 2; ++rh) {
            long r = rowbase + rt * 16 + rh * 8 + qr;
            if (r < MROWS) {
                float* orow = out + r * NL;
#pragma unroll
                for (int t = 0; t < 8; ++t) {
                    int c = t * 8 + qkc;
                    float2 v;
                    v.x = acc[rt][t][rh * 2 + 0] + bsm[c];
                    v.y = acc[rt][t][rh * 2 + 1] + bsm[c + 1];
                    *(float2*)(orow + c) = v;
                }
            }
        }
}

// ---------------- fused tree kernel: HMMA merge (R12 best: 84us) ----------------
#define EPITCH 34
#define TS_E    16384
#define TS_MBUF (TS_E + 256 * EPITCH * 8)            // 86016
#define TREE_SMEM_BYTES (TS_MBUF + 1024)             // 87040

__global__ __launch_bounds__(512) void tree_kernel(
    const float* __restrict__ emis, float* __restrict__ bufA,
    float* __restrict__ bufB, float* __restrict__ outg)
{
    uint4* Tsm = (uint4*)dynsm;
    float* Ebase = (float*)(dynsm + TS_E);           // pitch 68 floats per cv row
    float* mbuf = (float*)(dynsm + TS_MBUF);

    int t = threadIdx.x;
    int b = blockIdx.x;

    for (int i = t; i < 1024; i += 512) Tsm[i] = g_Tfrag[i];
    __syncthreads();

    const float* emisb = emis + (size_t)b * NNODES * NL;
    const float* prev  = emisb + (size_t)(LEAVES - 1) * NL;
    float* bufAb = bufA + (size_t)b * 512 * NL;
    float* bufBb = bufB + (size_t)b * 256 * NL;

    int lane = t & 31, w = t >> 5;
    int qr = lane >> 2, qk = lane & 3;
    int m0 = w * 16;
    bool gEven = (qr & 1) == 0;
    int sub = t & 3, cquad = t >> 2;

    for (int d = 9; d >= 0; --d) {
        int n = 1 << d;
        const float* emisLvl = emisb + (size_t)(n - 1) * NL;
        float* outLvl = (d == 0) ? (outg + (size_t)b * NL)
                                 : ((d & 1) ? bufAb : bufBb);
        int ntiles = (n + 127) >> 7;
        for (int tile = 0; tile < ntiles; ++tile) {
            int i0 = tile << 7;
            int NT = n - i0; if (NT > 128) NT = 128;
            int ncv = 2 * NT;

            // ---- phase 1: load children, per-cv max, exp, store f32 to E ----
            auto phase1 = [&](int co) {
                int c = co + cquad;
                bool valid = c < ncv;
                int cc = valid ? c : 0;
                const float* src = prev + (size_t)(i0 * 2 + cc) * NL + sub * 16;
                float4 v0 = *(const float4*)(src);
                float4 v1 = *(const float4*)(src + 4);
                float4 v2 = *(const float4*)(src + 8);
                float4 v3 = *(const float4*)(src + 12);
                float vv[16] = {v0.x, v0.y, v0.z, v0.w, v1.x, v1.y, v1.z, v1.w,
                                v2.x, v2.y, v2.z, v2.w, v3.x, v3.y, v3.z, v3.w};
                float m = vv[0];
#pragma unroll
                for (int j = 1; j < 16; ++j) m = fmaxf(m, vv[j]);
                m = fmaxf(m, __shfl_xor_sync(0xffffffffu, m, 1));
                m = fmaxf(m, __shfl_xor_sync(0xffffffffu, m, 2));
                if (valid) {
                    float* erow = Ebase + c * (EPITCH * 2) + sub * 16;
#pragma unroll
                    for (int j = 0; j < 4; ++j) {
                        float4 ev;
                        ev.x = __expf(vv[4 * j]     - m);
                        ev.y = __expf(vv[4 * j + 1] - m);
                        ev.z = __expf(vv[4 * j + 2] - m);
                        ev.w = __expf(vv[4 * j + 3] - m);
                        *(float4*)(erow + 4 * j) = ev;
                    }
                    if (sub == 0) mbuf[c] = m;
                }
            };
            phase1(0);
            if (ncv > 128) phase1(128);
            __syncthreads();

            // ---- phase 2: warp-level HMMA merge (warp owns 16 cv rows) ----
            if (m0 < ncv) {
                float acc[8][4];
#pragma unroll
                for (int nt = 0; nt < 8; ++nt)
#pragma unroll
                    for (int e = 0; e < 4; ++e) acc[nt][e] = 0.f;

#pragma unroll
                for (int s = 0; s < 4; ++s) {
                    const float* ep = Ebase + (m0 + qr) * (EPITCH * 2) + s * 16 + qk * 4;
                    float4 va = *(const float4*)(ep);
                    float4 vb = *(const float4*)(ep + 8 * EPITCH * 2);
                    uint32_t a0 = cvt_bf2(va.x, va.y);
                    uint32_t a1 = cvt_bf2(vb.x, vb.y);
                    uint32_t a2 = cvt_bf2(va.z, va.w);
                    uint32_t a3 = cvt_bf2(vb.z, vb.w);
#pragma unroll
                    for (int nt = 0; nt < 8; ++nt) {
                        uint4 wf = Tsm[(s * 8 + nt) * 32 + lane];
                        mma16816(acc[nt][0], acc[nt][1], acc[nt][2], acc[nt][3],
                                 a0, a1, a2, a3, wf.x, wf.y);   // hi
                        mma16816(acc[nt][0], acc[nt][1], acc[nt][2], acc[nt][3],
                                 a0, a1, a2, a3, wf.z, wf.w);   // lo
                    }
                }

                // ---- epilogue: log + m, combine L/R via shfl_xor(4), store ----
                int cvA = m0 + qr, cvB = m0 + qr + 8;
                float mA = mbuf[cvA], mB = mbuf[cvB];
                int nodeA = i0 + (cvA >> 1), nodeB = i0 + (cvB >> 1);
                int col = qk * 2;
#pragma unroll
                for (int nt = 0; nt < 8; ++nt) {
                    float l0 = __logf(acc[nt][0]) + mA;
                    float l1 = __logf(acc[nt][1]) + mA;
                    float l2 = __logf(acc[nt][2]) + mB;
                    float l3 = __logf(acc[nt][3]) + mB;
                    float o0 = __shfl_xor_sync(0xffffffffu, l0, 4);
                    float o1 = __shfl_xor_sync(0xffffffffu, l1, 4);
                    float o2 = __shfl_xor_sync(0xffffffffu, l2, 4);
                    float o3 = __shfl_xor_sync(0xffffffffu, l3, 4);
                    if (gEven) {
                        int c0 = nt * 8 + col;
                        if (cvA < ncv) {
                            float2 em = *(const float2*)(emisLvl + (size_t)nodeA * NL + c0);
                            float2 v; v.x = em.x + l0 + o0; v.y = em.y + l1 + o1;
                            *(float2*)(outLvl + (size_t)nodeA * NL + c0) = v;
                        }
                        if (cvB < ncv) {
                            float2 em = *(const float2*)(emisLvl + (size_t)nodeB * NL + c0);
                            float2 v; v.x = em.x + l2 + o2; v.y = em.y + l3 + o3;
                            *(float2*)(outLvl + (size_t)nodeB * NL + c0) = v;
                        }
                    }
                }
            }
            __syncthreads();
        }
        prev = outLvl;
    }
}

// ---------------- launch ----------------
extern "C" void kernel_launch(void* const* d_in, const int* in_sizes, int n_in,
                              void* d_out, int out_size)
{
    const float* hidden = (const float*)d_in[0];
    const float* W      = (const float*)d_in[1];
    const float* bias   = (const float*)d_in[2];
    const float* trans  = (const float*)d_in[3];
    float* out = (float*)d_out;

    float *emis, *bufA, *bufB;
    cudaGetSymbolAddress((void**)&emis, g_emis);
    cudaGetSymbolAddress((void**)&bufA, g_bufA);
    cudaGetSymbolAddress((void**)&bufB, g_bufB);

    init_kernel<<<(2048 + 32 * 4 * 32 + 255) / 256, 256>>>(trans, W);

    cudaFuncSetAttribute(gemm_kernel, cudaFuncAttributeMaxDynamicSharedMemorySize, GS_TOTAL);
    gemm_kernel<<<(MROWS + 511) / 512, 512, GS_TOTAL>>>(hidden, bias, emis);

    cudaFuncSetAttribute(tree_kernel, cudaFuncAttributeMaxDynamicSharedMemorySize, TREE_SMEM_BYTES);
    tree_kernel<<<B_SZ, 512, TREE_SMEM_BYTES>>>(emis, bufA, bufB, out);
}

// round 16
// speedup vs baseline: 1.3638x; 1.0302x over previous
#include <cuda_runtime.h>
#include <cuda_bf16.h>
#include <cstdint>

#define B_SZ   128
#define NNODES 2047
#define LEAVES 1024
#define DIN    512
#define NL     64
#define MROWS  (B_SZ * NNODES)          // 262016

typedef unsigned long long u64;

// ---------------- device scratch (static; no allocations) ----------------
__device__ float g_emis[(size_t)B_SZ * NNODES * NL];   // 67 MB
__device__ float g_bufA[(size_t)B_SZ * 512 * NL];      // odd levels
__device__ float g_bufB[(size_t)B_SZ * 256 * NL];      // even levels
__device__ uint4 g_Wfrag4[32 * 4 * 32];                // GEMM W frags, k-permuted
__device__ uint4 g_Tfrag[4 * 8 * 32];                  // tree expT frags {xh,yh,xl,yl}

// ---------------- packed helpers ----------------
__device__ __forceinline__ uint32_t cvt_bf2(float x0, float x1) {
    uint32_t h;
    asm("cvt.rn.satfinite.bf16x2.f32 %0, %1, %2;" : "=r"(h) : "f"(x1), "f"(x0));
    return h;
}
__device__ __forceinline__ void cvt_hilo(float x0, float x1, uint32_t& h, uint32_t& l) {
    asm("cvt.rn.satfinite.bf16x2.f32 %0, %1, %2;" : "=r"(h) : "f"(x1), "f"(x0));
    float r0 = x0 - __uint_as_float(h << 16);
    float r1 = x1 - __uint_as_float(h & 0xffff0000u);
    asm("cvt.rn.satfinite.bf16x2.f32 %0, %1, %2;" : "=r"(l) : "f"(r1), "f"(r0));
}
__device__ __forceinline__ void mma16816(float& d0, float& d1, float& d2, float& d3,
                                         uint32_t a0, uint32_t a1, uint32_t a2, uint32_t a3,
                                         uint32_t b0, uint32_t b1) {
    asm("mma.sync.aligned.m16n8k16.row.col.f32.bf16.bf16.f32 "
        "{%0,%1,%2,%3}, {%4,%5,%6,%7}, {%8,%9}, {%0,%1,%2,%3};"
        : "+f"(d0), "+f"(d1), "+f"(d2), "+f"(d3)
        : "r"(a0), "r"(a1), "r"(a2), "r"(a3), "r"(b0), "r"(b1));
}

// ---------------- init: GEMM W frags + tree expT frags (hi/lo) ----------------
__global__ void init_kernel(const float* __restrict__ trans, const float* __restrict__ W) {
    int i = blockIdx.x * blockDim.x + threadIdx.x;
    if (i < 4 * 8 * 32) {
        int lane = i & 31, nt = (i >> 5) & 7, s = i >> 8;
        int n  = nt * 8 + (lane >> 2);
        int k0 = s * 16 + (lane & 3) * 4;
        float t0 = expf(trans[n * NL + k0]);
        float t1 = expf(trans[n * NL + k0 + 1]);
        float t2 = expf(trans[n * NL + k0 + 2]);
        float t3 = expf(trans[n * NL + k0 + 3]);
        uint32_t xh, xl, yh, yl;
        cvt_hilo(t0, t1, xh, xl);
        cvt_hilo(t2, t3, yh, yl);
        g_Tfrag[i] = make_uint4(xh, yh, xl, yl);
    }
    int j = i - 2048;
    if (j >= 0 && j < 32 * 4 * 32) {
        int lane = j & 31, tp = (j >> 5) & 3, s = j >> 7;
        int k0 = s * 16 + (lane & 3) * 4;            // permuted: contiguous quad
        int n0 = (2 * tp) * 8 + (lane >> 2);
        int n1 = (2 * tp + 1) * 8 + (lane >> 2);
        uint32_t x0 = cvt_bf2(W[k0 * NL + n0],       W[(k0 + 1) * NL + n0]);
        uint32_t y0 = cvt_bf2(W[(k0 + 2) * NL + n0], W[(k0 + 3) * NL + n0]);
        uint32_t x1 = cvt_bf2(W[k0 * NL + n1],       W[(k0 + 1) * NL + n1]);
        uint32_t y1 = cvt_bf2(W[(k0 + 2) * NL + n1], W[(k0 + 3) * NL + n1]);
        g_Wfrag4[j] = make_uint4(x0, y0, x1, y1);
    }
}

// ---------------- HMMA emission GEMM (frozen R12 config) ----------------
#define GS_TOTAL (65536 + 256)

extern __shared__ char dynsm[];

__global__ __launch_bounds__(512) void gemm_kernel(
    const float* __restrict__ A, const float* __restrict__ bias,
    float* __restrict__ out)
{
    uint4* Wsm = (uint4*)dynsm;
    float* bsm = (float*)(dynsm + 65536);
    int tid = threadIdx.x;
    {
        const uint4* src = g_Wfrag4;
        for (int i = tid; i < 4096; i += 512) Wsm[i] = src[i];
        if (tid < NL) bsm[tid] = bias[tid];
    }
    __syncthreads();

    int lane = tid & 31, w = tid >> 5;
    long rowbase = (long)blockIdx.x * 512 + w * 32;
    int qr = lane >> 2;
    int qk = lane & 3;

    const float4* aptr[4];
#pragma unroll
    for (int rt = 0; rt < 2; ++rt)
#pragma unroll
        for (int rh = 0; rh < 2; ++rh) {
            long r = rowbase + rt * 16 + rh * 8 + qr;
            if (r > MROWS - 1) r = MROWS - 1;
            aptr[rt * 2 + rh] = (const float4*)(A + r * DIN) + qk;
        }

    float acc[2][8][4];
#pragma unroll
    for (int rt = 0; rt < 2; ++rt)
#pragma unroll
        for (int t = 0; t < 8; ++t)
#pragma unroll
            for (int e = 0; e < 4; ++e) acc[rt][t][e] = 0.f;

    float4 buf[2][4];
#pragma unroll
    for (int p = 0; p < 4; ++p) {
        buf[0][p] = aptr[p][0];
        buf[1][p] = aptr[p][4];
    }

#pragma unroll 1
    for (int s = 0; s < 32; ++s) {
        int pb = s & 1;
        uint32_t ah[2][4];
#pragma unroll
        for (int rt = 0; rt < 2; ++rt) {
            float4 v0 = buf[pb][2 * rt];
            float4 v1 = buf[pb][2 * rt + 1];
            ah[rt][0] = cvt_bf2(v0.x, v0.y);
            ah[rt][1] = cvt_bf2(v1.x, v1.y);
            ah[rt][2] = cvt_bf2(v0.z, v0.w);
            ah[rt][3] = cvt_bf2(v1.z, v1.w);
        }
        if (s + 2 < 32) {
#pragma unroll
            for (int p = 0; p < 4; ++p) buf[pb][p] = aptr[p][(s + 2) * 4];
        }
#pragma unroll
        for (int tp = 0; tp < 4; ++tp) {
            uint4 wb = Wsm[(s * 4 + tp) * 32 + lane];
#pragma unroll
            for (int rt = 0; rt < 2; ++rt) {
                mma16816(acc[rt][2*tp][0],   acc[rt][2*tp][1],   acc[rt][2*tp][2],   acc[rt][2*tp][3],
                         ah[rt][0], ah[rt][1], ah[rt][2], ah[rt][3], wb.x, wb.y);
                mma16816(acc[rt][2*tp+1][0], acc[rt][2*tp+1][1], acc[rt][2*tp+1][2], acc[rt][2*tp+1][3],
                         ah[rt][0], ah[rt][1], ah[rt][2], ah[rt][3], wb.z, wb.w);
            }
        }
    }

    int qkc = qk * 2;
#pragma unroll
    for (int rt = 0; rt < 2; ++rt)
#pragma unroll
        for (int rh = 0; rh < 2; ++rh) {
            long r = rowbase + rt * 16 + rh * 8 + qr;
            if (r < MROWS) {
                float* orow = out + r * NL;
#pragma unroll
                for (int t = 0; t < 8; ++t) {
                    int c = t * 8 + qkc;
                    float2 v;
                    v.x = acc[rt][t][rh * 2 + 0] + bsm[c];
                    v.y = acc[rt][t][rh * 2 + 1] + bsm[c + 1];
                    *(float2*)(orow + c) = v;
                }
            }
        }
}

// ---------------- tree common tile body ----------------
#define EPITCH 34
#define TS_E    16384
#define TS_MBUF (TS_E + 256 * EPITCH * 8)            // 86016
#define TREE_SMEM_BYTES (TS_MBUF + 1024)             // 87040

// ---------------- level-9 kernel: 512 independent full tiles ----------------
// Flat node space: level-9 node j = b*512+i; children are leaves 2j, 2j+1
// (2j = b*1024 + 2i). grid = 512, each block one full 128-node tile.
__global__ __launch_bounds__(512) void tree9_kernel(
    const float* __restrict__ emis, float* __restrict__ outp)
{
    uint4* Tsm = (uint4*)dynsm;
    float* Ebase = (float*)(dynsm + TS_E);
    float* mbuf = (float*)(dynsm + TS_MBUF);

    int t = threadIdx.x;
    for (int i = t; i < 1024; i += 512) Tsm[i] = g_Tfrag[i];

    int lane = t & 31, w = t >> 5;
    int qr = lane >> 2, qk = lane & 3;
    int m0 = w * 16;
    bool gEven = (qr & 1) == 0;
    int sub = t & 3, cquad = t >> 2;

    long j0 = (long)blockIdx.x * 128;

    // ---- phase 1 ----
#pragma unroll
    for (int co = 0; co < 256; co += 128) {
        int c = co + cquad;
        long jc = j0 * 2 + c;
        long b = jc >> 10, li = jc & 1023;
        const float* src = emis + (b * NNODES + (LEAVES - 1) + li) * NL + sub * 16;
        float4 v0 = *(const float4*)(src);
        float4 v1 = *(const float4*)(src + 4);
        float4 v2 = *(const float4*)(src + 8);
        float4 v3 = *(const float4*)(src + 12);
        float vv[16] = {v0.x, v0.y, v0.z, v0.w, v1.x, v1.y, v1.z, v1.w,
                        v2.x, v2.y, v2.z, v2.w, v3.x, v3.y, v3.z, v3.w};
        float m = vv[0];
#pragma unroll
        for (int j = 1; j < 16; ++j) m = fmaxf(m, vv[j]);
        m = fmaxf(m, __shfl_xor_sync(0xffffffffu, m, 1));
        m = fmaxf(m, __shfl_xor_sync(0xffffffffu, m, 2));
        float* erow = Ebase + c * (EPITCH * 2) + sub * 16;
#pragma unroll
        for (int j = 0; j < 4; ++j) {
            float4 ev;
            ev.x = __expf(vv[4 * j]     - m);
            ev.y = __expf(vv[4 * j + 1] - m);
            ev.z = __expf(vv[4 * j + 2] - m);
            ev.w = __expf(vv[4 * j + 3] - m);
            *(float4*)(erow + 4 * j) = ev;
        }
        if (sub == 0) mbuf[c] = m;
    }
    __syncthreads();

    // ---- phase 2 ----
    float acc[8][4];
#pragma unroll
    for (int nt = 0; nt < 8; ++nt)
#pragma unroll
        for (int e = 0; e < 4; ++e) acc[nt][e] = 0.f;

#pragma unroll
    for (int s = 0; s < 4; ++s) {
        const float* ep = Ebase + (m0 + qr) * (EPITCH * 2) + s * 16 + qk * 4;
        float4 va = *(const float4*)(ep);
        float4 vb = *(const float4*)(ep + 8 * EPITCH * 2);
        uint32_t a0 = cvt_bf2(va.x, va.y);
        uint32_t a1 = cvt_bf2(vb.x, vb.y);
        uint32_t a2 = cvt_bf2(va.z, va.w);
        uint32_t a3 = cvt_bf2(vb.z, vb.w);
#pragma unroll
        for (int nt = 0; nt < 8; ++nt) {
            uint4 wf = Tsm[(s * 8 + nt) * 32 + lane];
            mma16816(acc[nt][0], acc[nt][1], acc[nt][2], acc[nt][3],
                     a0, a1, a2, a3, wf.x, wf.y);
            mma16816(acc[nt][0], acc[nt][1], acc[nt][2], acc[nt][3],
                     a0, a1, a2, a3, wf.z, wf.w);
        }
    }

    // ---- epilogue ----
    int cvA = m0 + qr, cvB = m0 + qr + 8;
    float mA = mbuf[cvA], mB = mbuf[cvB];
    long jA = j0 + (cvA >> 1), jB = j0 + (cvB >> 1);
    long bA = jA >> 9, iA = jA & 511;
    long bB = jB >> 9, iB = jB & 511;
    const float* emisA = emis + (bA * NNODES + 511 + iA) * NL;
    const float* emisB = emis + (bB * NNODES + 511 + iB) * NL;
    float* outA = outp + jA * NL;
    float* outB = outp + jB * NL;
    int col = qk * 2;
#pragma unroll
    for (int nt = 0; nt < 8; ++nt) {
        float l0 = __logf(acc[nt][0]) + mA;
        float l1 = __logf(acc[nt][1]) + mA;
        float l2 = __logf(acc[nt][2]) + mB;
        float l3 = __logf(acc[nt][3]) + mB;
        float o0 = __shfl_xor_sync(0xffffffffu, l0, 4);
        float o1 = __shfl_xor_sync(0xffffffffu, l1, 4);
        float o2 = __shfl_xor_sync(0xffffffffu, l2, 4);
        float o3 = __shfl_xor_sync(0xffffffffu, l3, 4);
        if (gEven) {
            int c0 = nt * 8 + col;
            float2 emA = *(const float2*)(emisA + c0);
            float2 vA; vA.x = emA.x + l0 + o0; vA.y = emA.y + l1 + o1;
            *(float2*)(outA + c0) = vA;
            float2 emB = *(const float2*)(emisB + c0);
            float2 vB; vB.x = emB.x + l2 + o2; vB.y = emB.y + l3 + o3;
            *(float2*)(outB + c0) = vB;
        }
    }
}

// ---------------- fused tree kernel: levels 8..0, prev = bufA ----------------
__global__ __launch_bounds__(512) void tree_kernel(
    const float* __restrict__ emis, float* __restrict__ bufA,
    float* __restrict__ bufB, float* __restrict__ outg)
{
    uint4* Tsm = (uint4*)dynsm;
    float* Ebase = (float*)(dynsm + TS_E);
    float* mbuf = (float*)(dynsm + TS_MBUF);

    int t = threadIdx.x;
    int b = blockIdx.x;

    for (int i = t; i < 1024; i += 512) Tsm[i] = g_Tfrag[i];
    __syncthreads();

    const float* emisb = emis + (size_t)b * NNODES * NL;
    float* bufAb = bufA + (size_t)b * 512 * NL;
    float* bufBb = bufB + (size_t)b * 256 * NL;
    const float* prev = bufAb;           // level-9 results (from tree9_kernel)

    int lane = t & 31, w = t >> 5;
    int qr = lane >> 2, qk = lane & 3;
    int m0 = w * 16;
    bool gEven = (qr & 1) == 0;
    int sub = t & 3, cquad = t >> 2;

    for (int d = 8; d >= 0; --d) {
        int n = 1 << d;
        const float* emisLvl = emisb + (size_t)(n - 1) * NL;
        float* outLvl = (d == 0) ? (outg + (size_t)b * NL)
                                 : ((d & 1) ? bufAb : bufBb);
        int ntiles = (n + 127) >> 7;
        for (int tile = 0; tile < ntiles; ++tile) {
            int i0 = tile << 7;
            int NT = n - i0; if (NT > 128) NT = 128;
            int ncv = 2 * NT;

            // ---- phase 1 ----
            auto phase1 = [&](int co) {
                int c = co + cquad;
                bool valid = c < ncv;
                int cc = valid ? c : 0;
                const float* src = prev + (size_t)(i0 * 2 + cc) * NL + sub * 16;
                float4 v0 = *(const float4*)(src);
                float4 v1 = *(const float4*)(src + 4);
                float4 v2 = *(const float4*)(src + 8);
                float4 v3 = *(const float4*)(src + 12);
                float vv[16] = {v0.x, v0.y, v0.z, v0.w, v1.x, v1.y, v1.z, v1.w,
                                v2.x, v2.y, v2.z, v2.w, v3.x, v3.y, v3.z, v3.w};
                float m = vv[0];
#pragma unroll
                for (int j = 1; j < 16; ++j) m = fmaxf(m, vv[j]);
                m = fmaxf(m, __shfl_xor_sync(0xffffffffu, m, 1));
                m = fmaxf(m, __shfl_xor_sync(0xffffffffu, m, 2));
                if (valid) {
                    float* erow = Ebase + c * (EPITCH * 2) + sub * 16;
#pragma unroll
                    for (int j = 0; j < 4; ++j) {
                        float4 ev;
                        ev.x = __expf(vv[4 * j]     - m);
                        ev.y = __expf(vv[4 * j + 1] - m);
                        ev.z = __expf(vv[4 * j + 2] - m);
                        ev.w = __expf(vv[4 * j + 3] - m);
                        *(float4*)(erow + 4 * j) = ev;
                    }
                    if (sub == 0) mbuf[c] = m;
                }
            };
            phase1(0);
            if (ncv > 128) phase1(128);
            __syncthreads();

            // ---- phase 2 ----
            if (m0 < ncv) {
                float acc[8][4];
#pragma unroll
                for (int nt = 0; nt < 8; ++nt)
#pragma unroll
                    for (int e = 0; e < 4; ++e) acc[nt][e] = 0.f;

#pragma unroll
                for (int s = 0; s < 4; ++s) {
                    const float* ep = Ebase + (m0 + qr) * (EPITCH * 2) + s * 16 + qk * 4;
                    float4 va = *(const float4*)(ep);
                    float4 vb = *(const float4*)(ep + 8 * EPITCH * 2);
                    uint32_t a0 = cvt_bf2(va.x, va.y);
                    uint32_t a1 = cvt_bf2(vb.x, vb.y);
                    uint32_t a2 = cvt_bf2(va.z, va.w);
                    uint32_t a3 = cvt_bf2(vb.z, vb.w);
#pragma unroll
                    for (int nt = 0; nt < 8; ++nt) {
                        uint4 wf = Tsm[(s * 8 + nt) * 32 + lane];
                        mma16816(acc[nt][0], acc[nt][1], acc[nt][2], acc[nt][3],
                                 a0, a1, a2, a3, wf.x, wf.y);
                        mma16816(acc[nt][0], acc[nt][1], acc[nt][2], acc[nt][3],
                                 a0, a1, a2, a3, wf.z, wf.w);
                    }
                }

                // ---- epilogue ----
                int cvA = m0 + qr, cvB = m0 + qr + 8;
                float mA = mbuf[cvA], mB = mbuf[cvB];
                int nodeA = i0 + (cvA >> 1), nodeB = i0 + (cvB >> 1);
                int col = qk * 2;
#pragma unroll
                for (int nt = 0; nt < 8; ++nt) {
                    float l0 = __logf(acc[nt][0]) + mA;
                    float l1 = __logf(acc[nt][1]) + mA;
                    float l2 = __logf(acc[nt][2]) + mB;
                    float l3 = __logf(acc[nt][3]) + mB;
                    float o0 = __shfl_xor_sync(0xffffffffu, l0, 4);
                    float o1 = __shfl_xor_sync(0xffffffffu, l1, 4);
                    float o2 = __shfl_xor_sync(0xffffffffu, l2, 4);
                    float o3 = __shfl_xor_sync(0xffffffffu, l3, 4);
                    if (gEven) {
                        int c0 = nt * 8 + col;
                        if (cvA < ncv) {
                            float2 em = *(const float2*)(emisLvl + (size_t)nodeA * NL + c0);
                            float2 v; v.x = em.x + l0 + o0; v.y = em.y + l1 + o1;
                            *(float2*)(outLvl + (size_t)nodeA * NL + c0) = v;
                        }
                        if (cvB < ncv) {
                            float2 em = *(const float2*)(emisLvl + (size_t)nodeB * NL + c0);
                            float2 v; v.x = em.x + l2 + o2; v.y = em.y + l3 + o3;
                            *(float2*)(outLvl + (size_t)nodeB * NL + c0) = v;
                        }
                    }
                }
            }
            __syncthreads();
        }
        prev = outLvl;
    }
}

// ---------------- launch ----------------
extern "C" void kernel_launch(void* const* d_in, const int* in_sizes, int n_in,
                              void* d_out, int out_size)
{
    const float* hidden = (const float*)d_in[0];
    const float* W      = (const float*)d_in[1];
    const float* bias   = (const float*)d_in[2];
    const float* trans  = (const float*)d_in[3];
    float* out = (float*)d_out;

    float *emis, *bufA, *bufB;
    cudaGetSymbolAddress((void**)&emis, g_emis);
    cudaGetSymbolAddress((void**)&bufA, g_bufA);
    cudaGetSymbolAddress((void**)&bufB, g_bufB);

    init_kernel<<<(2048 + 32 * 4 * 32 + 255) / 256, 256>>>(trans, W);

    cudaFuncSetAttribute(gemm_kernel, cudaFuncAttributeMaxDynamicSharedMemorySize, GS_TOTAL);
    gemm_kernel<<<(MROWS + 511) / 512, 512, GS_TOTAL>>>(hidden, bias, emis);

    cudaFuncSetAttribute(tree9_kernel, cudaFuncAttributeMaxDynamicSharedMemorySize, TREE_SMEM_BYTES);
    tree9_kernel<<<512, 512, TREE_SMEM_BYTES>>>(emis, bufA);

    cudaFuncSetAttribute(tree_kernel, cudaFuncAttributeMaxDynamicSharedMemorySize, TREE_SMEM_BYTES);
    tree_kernel<<<B_SZ, 512, TREE_SMEM_BYTES>>>(emis, bufA, bufB, out);
}